// round 4
// baseline (speedup 1.0000x reference)
#include <cuda_runtime.h>
#include <math.h>

#define NFEAT 64
#define NNODES 50000
#define TS 65              // staging row stride: 65 mod 32 = 1 -> conflict-free scalar access

// Scratch (device globals; no allocation allowed)
__device__ float g_agg[NNODES * NFEAT];          // aggregated edge features
__device__ float g_preR[NNODES * 128];           // [PE_src | PA_src] per node
__device__ float g_preC[NNODES * 128];           // [PE_tgt | PA_tgt] per node

// Branchless tanhshrink: x - tanh(x), no cancellation.
// |x| < 0.5 : x^3*(1/3 - 2/15 x^2 + 17/315 x^4)   (trunc err < 5e-5)
// |x| >= 0.5: |x| - 1 + 2/(exp(2|x|)+1), sign restored.
__device__ __forceinline__ float tshrink(float x) {
    float ax = fabsf(x);
    float x2 = x * x;
    float p = 0.33333333f + x2 * (-0.13333333f + x2 * 0.05396825f);
    float small = x * x2 * p;
    float e = __expf(2.0f * ax);
    float big = ax - 1.0f + __fdividef(2.0f, e + 1.0f);
    big = copysignf(big, x);
    return ax < 0.5f ? small : big;
}

__device__ __forceinline__ float sigmoidf_fast(float x) {
    return __fdividef(1.0f, 1.0f + __expf(-x));
}

// acc[0..63] += x * w[0..63], weights from GLOBAL (uniform -> L1 broadcast)
__device__ __forceinline__ void fma_one_g(float x, const float* __restrict__ w, float* acc) {
    const float4* w4 = (const float4*)w;
#pragma unroll
    for (int j = 0; j < 16; j++) {
        float4 t = __ldg(&w4[j]);
        acc[4*j+0] += x * t.x; acc[4*j+1] += x * t.y;
        acc[4*j+2] += x * t.z; acc[4*j+3] += x * t.w;
    }
}

// acc[0..63] += x * w[0..63], weights from SHARED (uniform -> broadcast)
__device__ __forceinline__ void fma_one_sh(float x, const float* w, float* acc) {
    const float4* w4 = (const float4*)w;
#pragma unroll
    for (int j = 0; j < 16; j++) {
        float4 t = w4[j];
        acc[4*j+0] += x * t.x; acc[4*j+1] += x * t.y;
        acc[4*j+2] += x * t.z; acc[4*j+3] += x * t.w;
    }
}

__device__ __forceinline__ void init_from_bias(const float* __restrict__ b, float* acc) {
    const float4* b4 = (const float4*)b;
#pragma unroll
    for (int j = 0; j < 16; j++) {
        float4 t = __ldg(&b4[j]);
        acc[4*j+0] = t.x; acc[4*j+1] = t.y; acc[4*j+2] = t.z; acc[4*j+3] = t.w;
    }
}

// ---------------------------------------------------------------------------
// Warp-cooperative stage of one 64-float half-row per edge, SUMMED from two
// tables: buf_row(i) = A[ai*128 + off + k] + B[bi*128 + off + k], k=0..63.
// Pair scheme: lanes 0-15 edge 2p, lanes 16-31 edge 2p+1. Coalesced LDG.128.
// ---------------------------------------------------------------------------
__device__ __forceinline__ void coop_stage_sum(
    float* wbuf, const float* __restrict__ A, const float* __restrict__ B,
    int a_idx, int b_idx, int off4, int lane) {
    int half = lane >> 4;
    int sub  = lane & 15;
#pragma unroll 1
    for (int p = 0; p < 16; p++) {
        int i0 = 2 * p, i1 = 2 * p + 1;
        int ra = __shfl_sync(0xffffffffu, a_idx, i0);
        int rb = __shfl_sync(0xffffffffu, a_idx, i1);
        int ca = __shfl_sync(0xffffffffu, b_idx, i0);
        int cb = __shfl_sync(0xffffffffu, b_idx, i1);
        int ri  = half ? rb : ra;
        int ci  = half ? cb : ca;
        int row = half ? i1 : i0;
        float4 a = __ldg((const float4*)(A + (size_t)ri * 128) + off4 + sub);
        float4 b = __ldg((const float4*)(B + (size_t)ci * 128) + off4 + sub);
        float* dst = wbuf + row * TS + 4 * sub;
        dst[0] = a.x + b.x; dst[1] = a.y + b.y;
        dst[2] = a.z + b.z; dst[3] = a.w + b.w;
    }
}

// Cooperative stage of one 64-float row per thread from a [n,64] table.
__device__ __forceinline__ void coop_stage_row64(
    float* wbuf, const float* __restrict__ A, int idx, int lane) {
    int half = lane >> 4;
    int sub  = lane & 15;
#pragma unroll 1
    for (int p = 0; p < 16; p++) {
        int i0 = 2 * p, i1 = 2 * p + 1;
        int ia = __shfl_sync(0xffffffffu, idx, i0);
        int ib = __shfl_sync(0xffffffffu, idx, i1);
        int ii  = half ? ib : ia;
        int row = half ? i1 : i0;
        float4 a = __ldg((const float4*)(A + (size_t)ii * 64) + sub);
        float* dst = wbuf + row * TS + 4 * sub;
        dst[0] = a.x; dst[1] = a.y; dst[2] = a.z; dst[3] = a.w;
    }
}

// ---------------------------------------------------------------------------
// Init: zero agg buffer, seed coord_out = coord
// ---------------------------------------------------------------------------
__global__ void init_kernel(const float* __restrict__ coord, float* __restrict__ coord_out,
                            int n) {
    int i = blockIdx.x * blockDim.x + threadIdx.x;
    if (i < n * NFEAT) g_agg[i] = 0.0f;
    if (i < n * 3) coord_out[i] = coord[i];
}

// ---------------------------------------------------------------------------
// Precompute per-node projections (see R2). Cooperative row I/O.
// ---------------------------------------------------------------------------
__global__ __launch_bounds__(256) void pre_kernel(
    const float* __restrict__ nodes,
    const float* __restrict__ eW1, const float* __restrict__ aW1, int n) {
    extern __shared__ float sm[];
    int t = threadIdx.x, lane = t & 31, wid = t >> 5;
    float* wbuf = sm + (wid * 32) * TS;
    float* my   = wbuf + lane * TS;

    int i = blockIdx.x * 256 + t;
    int ii = i < n ? i : (n - 1);
    bool valid = i < n;

    // stage node row cooperatively
    coop_stage_row64(wbuf, nodes, ii, lane);
    __syncwarp();

    float x[64];
#pragma unroll
    for (int k = 0; k < 64; k++) x[k] = my[k];

    float acc[64];
    const float* Ws[4] = { eW1, aW1, eW1 + 64 * 64, aW1 + 64 * 64 };
    float* outs[4] = { g_preR + (size_t)ii * 128,      g_preR + (size_t)ii * 128 + 64,
                       g_preC + (size_t)ii * 128,      g_preC + (size_t)ii * 128 + 64 };
    (void)outs;

#pragma unroll 1
    for (int m = 0; m < 4; m++) {
#pragma unroll
        for (int j = 0; j < 64; j++) acc[j] = 0.0f;
        const float* W = Ws[m];
#pragma unroll 1
        for (int k = 0; k < 64; k++) fma_one_g(x[k], W + k * 64, acc);
        // stage result, write cooperatively (coalesced)
        __syncwarp();
#pragma unroll
        for (int j = 0; j < 64; j++) my[j] = acc[j];
        __syncwarp();
        {
            int half = lane >> 4, sub = lane & 15;
            float* base = (m < 2) ? g_preR : g_preC;
            int off4 = (m & 1) ? 16 : 0;
#pragma unroll 1
            for (int p = 0; p < 16; p++) {
                int i0 = 2 * p, i1 = 2 * p + 1;
                int row = half ? i1 : i0;
                int gidx = blockIdx.x * 256 + wid * 32 + row;
                if (gidx < n) {
                    float* src = wbuf + row * TS + 4 * sub;
                    float4 v = make_float4(src[0], src[1], src[2], src[3]);
                    *((float4*)(base + (size_t)gidx * 128) + off4 + sub) = v;
                }
            }
        }
    }
    (void)valid;
}

// ---------------------------------------------------------------------------
// Edge kernel: thread-per-edge GEMVs, warp-cooperative gathers.
// ---------------------------------------------------------------------------
#define SM_W2   0
#define SM_C1   4096
#define SM_MISC 8192
#define SM_BUF  8704

__global__ __launch_bounds__(256) void edge_kernel(
    const float* __restrict__ coord,
    const int*   __restrict__ edges,
    const float* __restrict__ eW1, const float* __restrict__ eb1,
    const float* __restrict__ eW2, const float* __restrict__ eb2,
    const float* __restrict__ ab1,
    const float* __restrict__ aW2, const float* __restrict__ ab2,
    const float* __restrict__ cW1, const float* __restrict__ cb1,
    const float* __restrict__ cW2, const float* __restrict__ cb2,
    float* __restrict__ coord_out, int n_edges) {
    extern __shared__ float sm[];
    int t = threadIdx.x, lane = t & 31, wid = t >> 5;

    for (int i = t; i < 4096; i += 256) { sm[SM_W2 + i] = eW2[i]; sm[SM_C1 + i] = cW1[i]; }
    if (t < 64) {
        sm[SM_MISC +       t] = eb1[t];
        sm[SM_MISC +  64 + t] = eW1[128 * 64 + t];   // radial row
        sm[SM_MISC + 128 + t] = ab1[t];
        sm[SM_MISC + 192 + t] = aW2[t];
        sm[SM_MISC + 256 + t] = eb2[t];
        sm[SM_MISC + 320 + t] = cb1[t];
        sm[SM_MISC + 384 + t] = cW2[t];
    }
    if (t == 0) { sm[SM_MISC + 448] = ab2[0]; sm[SM_MISC + 449] = cb2[0]; }
    __syncthreads();

    const float* eb1s  = sm + SM_MISC;
    const float* w128s = sm + SM_MISC + 64;
    const float* ab1s  = sm + SM_MISC + 128;
    const float* aW2s  = sm + SM_MISC + 192;
    const float* eb2s  = sm + SM_MISC + 256;
    const float* cb1s  = sm + SM_MISC + 320;
    const float* cW2s  = sm + SM_MISC + 384;
    float* wbuf = sm + SM_BUF + (wid * 32) * TS;
    float* my   = wbuf + lane * TS;

    int e = blockIdx.x * 256 + t;             // 800000 % 256 == 0: no tail
    int r = edges[e];
    int c = edges[n_edges + e];

    float d0 = coord[3*r+0] - coord[3*c+0];
    float d1 = coord[3*r+1] - coord[3*c+1];
    float d2 = coord[3*r+2] - coord[3*c+2];
    float radial = d0*d0 + d1*d1 + d2*d2;

    // ---- stage ATT inputs (pr_att + pc_att) cooperatively ----
    coop_stage_sum(wbuf, g_preR, g_preC, r, c, /*off4=*/16, lane);
    __syncwarp();

    float s_att = sm[SM_MISC + 448];
#pragma unroll 1
    for (int k = 0; k < 64; k++) {
        float x = my[k] + ab1s[k];
        s_att += tshrink(x) * aW2s[k];
    }
    float gate = sigmoidf_fast(s_att);
    __syncwarp();

    // ---- stage HIDDEN inputs (pr_h + pc_h) cooperatively ----
    coop_stage_sum(wbuf, g_preR, g_preC, r, c, /*off4=*/0, lane);
    __syncwarp();

    // per-thread: h = tanhshrink(sum + radial*w128 + eb1), in place
#pragma unroll 1
    for (int k = 0; k < 64; k++)
        my[k] = tshrink(fmaf(radial, w128s[k], my[k] + eb1s[k]));

    // ---- edge MLP layer 2 (GEMV, shared weights) ----
    float acc[64];
#pragma unroll
    for (int j = 0; j < 64; j++) acc[j] = eb2s[j];
#pragma unroll 1
    for (int k = 0; k < 64; k++) fma_one_sh(my[k], sm + SM_W2 + k * 64, acc);

    // ---- gate + scatter edge_feat, restage ----
    float* aggRow = g_agg + (size_t)r * 64;
#pragma unroll
    for (int j = 0; j < 16; j++) {
        float f0 = tshrink(acc[4*j+0]) * gate;
        float f1 = tshrink(acc[4*j+1]) * gate;
        float f2 = tshrink(acc[4*j+2]) * gate;
        float f3 = tshrink(acc[4*j+3]) * gate;
        my[4*j+0] = f0; my[4*j+1] = f1; my[4*j+2] = f2; my[4*j+3] = f3;
        asm volatile("red.global.add.v4.f32 [%0], {%1,%2,%3,%4};"
                     :: "l"(aggRow + 4*j), "f"(f0), "f"(f1), "f"(f2), "f"(f3)
                     : "memory");
    }

    // ---- coord MLP layer 1 (GEMV, shared weights) ----
#pragma unroll
    for (int j = 0; j < 64; j++) acc[j] = cb1s[j];
#pragma unroll 1
    for (int k = 0; k < 64; k++) fma_one_sh(my[k], sm + SM_C1 + k * 64, acc);

    float sc = sm[SM_MISC + 449];
#pragma unroll 1
    for (int k = 0; k < 64; k++) sc += tshrink(acc[k]) * cW2s[k];

    atomicAdd(&coord_out[3*r+0], d0 * sc);
    atomicAdd(&coord_out[3*r+1], d1 * sc);
    atomicAdd(&coord_out[3*r+2], d2 * sc);
}

// ---------------------------------------------------------------------------
// Node kernel: out = nodes + tanhshrink([nodes|agg] @ nW1 + nb1) @ nW2 + nb2
// Cooperative row I/O; single accumulator array for register pressure.
// ---------------------------------------------------------------------------
__global__ __launch_bounds__(256) void node_kernel(
    const float* __restrict__ nodes,
    const float* __restrict__ nW1, const float* __restrict__ nb1,
    const float* __restrict__ nW2, const float* __restrict__ nb2,
    float* __restrict__ out, int n) {
    extern __shared__ float sm[];
    int t = threadIdx.x, lane = t & 31, wid = t >> 5;
    float* wbuf = sm + (wid * 32) * TS;
    float* my   = wbuf + lane * TS;

    int i = blockIdx.x * 256 + t;
    int ii = i < n ? i : (n - 1);

    float acc[64];
    init_from_bias(nb1, acc);

    // half 1: nodes row
    coop_stage_row64(wbuf, nodes, ii, lane);
    __syncwarp();
#pragma unroll 1
    for (int k = 0; k < 64; k++) fma_one_g(my[k], nW1 + k * 64, acc);
    __syncwarp();

    // half 2: agg row
    coop_stage_row64(wbuf, g_agg, ii, lane);
    __syncwarp();
#pragma unroll 1
    for (int k = 0; k < 64; k++) fma_one_g(my[k], nW1 + (64 + k) * 64, acc);

    // activation into staging, second GEMV
#pragma unroll
    for (int k = 0; k < 64; k++) my[k] = tshrink(acc[k]);
    init_from_bias(nb2, acc);
#pragma unroll 1
    for (int k = 0; k < 64; k++) fma_one_g(my[k], nW2 + k * 64, acc);

    // stage result, cooperative residual + write (coalesced)
    __syncwarp();
#pragma unroll
    for (int j = 0; j < 64; j++) my[j] = acc[j];
    __syncwarp();
    {
        int half = lane >> 4, sub = lane & 15;
#pragma unroll 1
        for (int p = 0; p < 16; p++) {
            int i0 = 2 * p, i1 = 2 * p + 1;
            int row = half ? i1 : i0;
            int gidx = blockIdx.x * 256 + wid * 32 + row;
            if (gidx < n) {
                float4 nv = __ldg((const float4*)(nodes + (size_t)gidx * 64) + sub);
                float* src = wbuf + row * TS + 4 * sub;
                float4 w = make_float4(nv.x + src[0], nv.y + src[1],
                                       nv.z + src[2], nv.w + src[3]);
                *((float4*)(out + (size_t)gidx * 64) + sub) = w;
            }
        }
    }
}

// ---------------------------------------------------------------------------
extern "C" void kernel_launch(void* const* d_in, const int* in_sizes, int n_in,
                              void* d_out, int out_size) {
    const float* nodes = (const float*)d_in[0];
    const float* coord = (const float*)d_in[1];
    const int*   edges = (const int*)d_in[2];
    const float* eW1 = (const float*)d_in[3];
    const float* eb1 = (const float*)d_in[4];
    const float* eW2 = (const float*)d_in[5];
    const float* eb2 = (const float*)d_in[6];
    const float* aW1 = (const float*)d_in[7];
    const float* ab1 = (const float*)d_in[8];
    const float* aW2 = (const float*)d_in[9];
    const float* ab2 = (const float*)d_in[10];
    const float* nW1 = (const float*)d_in[11];
    const float* nb1 = (const float*)d_in[12];
    const float* nW2 = (const float*)d_in[13];
    const float* nb2 = (const float*)d_in[14];
    const float* cW1 = (const float*)d_in[15];
    const float* cb1 = (const float*)d_in[16];
    const float* cW2 = (const float*)d_in[17];
    const float* cb2 = (const float*)d_in[18];

    int n = in_sizes[0] / NFEAT;            // 50000
    int n_edges = in_sizes[2] / 2;          // 800000

    float* out = (float*)d_out;
    float* nodes_out = out;
    float* coord_out = out + (size_t)n * NFEAT;

    const size_t smem_stage = (size_t)(256 * TS) * sizeof(float);           // 66.56 KB
    const size_t smem_edge  = (size_t)(8704 + 256 * TS) * sizeof(float);    // ~101 KB
    cudaFuncSetAttribute(pre_kernel,  cudaFuncAttributeMaxDynamicSharedMemorySize, (int)smem_stage);
    cudaFuncSetAttribute(edge_kernel, cudaFuncAttributeMaxDynamicSharedMemorySize, (int)smem_edge);
    cudaFuncSetAttribute(node_kernel, cudaFuncAttributeMaxDynamicSharedMemorySize, (int)smem_stage);

    int init_blocks = (n * NFEAT + 255) / 256;
    init_kernel<<<init_blocks, 256>>>(coord, coord_out, n);

    int nblocks = (n + 255) / 256;
    pre_kernel<<<nblocks, 256, smem_stage>>>(nodes, eW1, aW1, n);

    int edge_blocks = (n_edges + 255) / 256;
    edge_kernel<<<edge_blocks, 256, smem_edge>>>(
        coord, edges,
        eW1, eb1, eW2, eb2,
        ab1, aW2, ab2,
        cW1, cb1, cW2, cb2,
        coord_out, n_edges);

    node_kernel<<<nblocks, 256, smem_stage>>>(
        nodes, nW1, nb1, nW2, nb2, nodes_out, n);
}

// round 5
// speedup vs baseline: 1.3802x; 1.3802x over previous
#include <cuda_runtime.h>
#include <math.h>

#define NFEAT 64
#define NNODES 50000
#define TS 65              // staging stride: 65 mod 32 = 1 -> conflict-free

// Scratch (device globals; no allocation allowed)
__device__ float g_agg[NNODES * NFEAT];          // aggregated edge features
__device__ float g_preR[NNODES * 128];           // [PE_src | PA_src] per node
__device__ float g_preC[NNODES * 128];           // [PE_tgt | PA_tgt] per node

// Branchless tanhshrink: x - tanh(x), computed WITHOUT cancellation.
// |x| < 0.55 : Taylor x^3*(1/3 - 2/15 x^2 + 17/315 x^4 - 62/2835 x^6 + 1382/155925 x^8)
// |x| >= 0.55: |x| - 1 + 2/(exp(2|x|)+1), sign restored.
__device__ __forceinline__ float tshrink(float x) {
    float ax = fabsf(x);
    float x2 = x * x;
    float p = 0.33333333f + x2 * (-0.13333333f + x2 * (0.05396825f
              + x2 * (-0.02186949f + x2 * 0.00886324f)));
    float small = x * x2 * p;
    float e = __expf(2.0f * ax);
    float big = ax - 1.0f + __fdividef(2.0f, e + 1.0f);
    big = copysignf(big, x);
    return ax < 0.55f ? small : big;
}

__device__ __forceinline__ float sigmoidf_fast(float x) {
    return __fdividef(1.0f, 1.0f + __expf(-x));
}

// acc[0..63] += x * w[0..63], weights from GLOBAL (uniform -> L1 broadcast)
__device__ __forceinline__ void fma_one_g(float x, const float* __restrict__ w, float* acc) {
    const float4* w4 = (const float4*)w;
#pragma unroll
    for (int j = 0; j < 16; j++) {
        float4 t = __ldg(&w4[j]);
        acc[4*j+0] += x * t.x; acc[4*j+1] += x * t.y;
        acc[4*j+2] += x * t.z; acc[4*j+3] += x * t.w;
    }
}

// acc[0..63] += x * w[0..63], weights from SHARED (uniform -> broadcast)
__device__ __forceinline__ void fma_one_sh(float x, const float* w, float* acc) {
    const float4* w4 = (const float4*)w;
#pragma unroll
    for (int j = 0; j < 16; j++) {
        float4 t = w4[j];
        acc[4*j+0] += x * t.x; acc[4*j+1] += x * t.y;
        acc[4*j+2] += x * t.z; acc[4*j+3] += x * t.w;
    }
}

__device__ __forceinline__ void init_from_bias(const float* __restrict__ b, float* acc) {
    const float4* b4 = (const float4*)b;
#pragma unroll
    for (int j = 0; j < 16; j++) {
        float4 t = __ldg(&b4[j]);
        acc[4*j+0] = t.x; acc[4*j+1] = t.y; acc[4*j+2] = t.z; acc[4*j+3] = t.w;
    }
}

// ---------------------------------------------------------------------------
// Init: zero agg buffer, seed coord_out = coord
// ---------------------------------------------------------------------------
__global__ void init_kernel(const float* __restrict__ coord, float* __restrict__ coord_out,
                            int n) {
    int i = blockIdx.x * blockDim.x + threadIdx.x;
    if (i < n * NFEAT) g_agg[i] = 0.0f;
    if (i < n * 3) coord_out[i] = coord[i];
}

// ---------------------------------------------------------------------------
// Precompute per-node projections, split by role half (blockIdx.y):
//   y=0: g_preR[i] = [ nodes[i] @ eW1[0:64]   | nodes[i] @ aW1[0:64]   ]
//   y=1: g_preC[i] = [ nodes[i] @ eW1[64:128] | nodes[i] @ aW1[64:128] ]
// Weights for this half staged in shared (2x 16KB); x staged per thread.
// ---------------------------------------------------------------------------
__global__ __launch_bounds__(256) void pre_kernel(
    const float* __restrict__ nodes,
    const float* __restrict__ eW1, const float* __restrict__ aW1, int n) {
    extern __shared__ float sm[];
    float* sWE = sm;            // 64x64
    float* sWA = sm + 4096;     // 64x64
    float* stage = sm + 8192;   // 256*TS

    int t = threadIdx.x;
    int part = blockIdx.y;                     // 0 = src half, 1 = tgt half
    const float* WE = eW1 + part * 64 * 64;
    const float* WA = aW1 + part * 64 * 64;
    for (int i = t; i < 4096; i += 256) { sWE[i] = WE[i]; sWA[i] = WA[i]; }
    __syncthreads();

    int i = blockIdx.x * 256 + t;
    if (i >= n) return;
    float* my = stage + t * TS;

    // stage x row (per-thread float4 loads)
    const float4* nod4 = (const float4*)nodes;
    size_t base = (size_t)i * 16;
#pragma unroll
    for (int j = 0; j < 16; j++) {
        float4 v = __ldg(&nod4[base + j]);
        my[4*j+0] = v.x; my[4*j+1] = v.y; my[4*j+2] = v.z; my[4*j+3] = v.w;
    }

    float acc[64];
    float4* outp = (float4*)((part == 0 ? g_preR : g_preC) + (size_t)i * 128);

    // E projection
#pragma unroll
    for (int j = 0; j < 64; j++) acc[j] = 0.0f;
#pragma unroll 2
    for (int k = 0; k < 64; k++) fma_one_sh(my[k], sWE + k * 64, acc);
#pragma unroll
    for (int j = 0; j < 16; j++)
        outp[j] = make_float4(acc[4*j], acc[4*j+1], acc[4*j+2], acc[4*j+3]);

    // A projection
#pragma unroll
    for (int j = 0; j < 64; j++) acc[j] = 0.0f;
#pragma unroll 2
    for (int k = 0; k < 64; k++) fma_one_sh(my[k], sWA + k * 64, acc);
#pragma unroll
    for (int j = 0; j < 16; j++)
        outp[16 + j] = make_float4(acc[4*j], acc[4*j+1], acc[4*j+2], acc[4*j+3]);
}

// ---------------------------------------------------------------------------
// Edge kernel: one thread per edge, precomputed projections (R2 structure).
// ---------------------------------------------------------------------------
#define SM_W2   0
#define SM_C1   4096
#define SM_MISC 8192
#define SM_BUF  8704

__global__ __launch_bounds__(256) void edge_kernel(
    const float* __restrict__ coord,
    const int*   __restrict__ edges,
    const float* __restrict__ eW1, const float* __restrict__ eb1,
    const float* __restrict__ eW2, const float* __restrict__ eb2,
    const float* __restrict__ ab1,
    const float* __restrict__ aW2, const float* __restrict__ ab2,
    const float* __restrict__ cW1, const float* __restrict__ cb1,
    const float* __restrict__ cW2, const float* __restrict__ cb2,
    float* __restrict__ coord_out, int n_edges) {
    extern __shared__ float sm[];
    int t = threadIdx.x;

    for (int i = t; i < 4096; i += 256) { sm[SM_W2 + i] = eW2[i]; sm[SM_C1 + i] = cW1[i]; }
    if (t < 64) {
        sm[SM_MISC +       t] = eb1[t];
        sm[SM_MISC +  64 + t] = eW1[128 * 64 + t];   // radial row
        sm[SM_MISC + 128 + t] = ab1[t];
        sm[SM_MISC + 192 + t] = aW2[t];
        sm[SM_MISC + 256 + t] = eb2[t];
        sm[SM_MISC + 320 + t] = cb1[t];
        sm[SM_MISC + 384 + t] = cW2[t];
    }
    if (t == 0) { sm[SM_MISC + 448] = ab2[0]; sm[SM_MISC + 449] = cb2[0]; }
    __syncthreads();

    const float* eb1s  = sm + SM_MISC;
    const float* w128s = sm + SM_MISC + 64;
    const float* ab1s  = sm + SM_MISC + 128;
    const float* aW2s  = sm + SM_MISC + 192;
    const float* eb2s  = sm + SM_MISC + 256;
    const float* cb1s  = sm + SM_MISC + 320;
    const float* cW2s  = sm + SM_MISC + 384;
    float* my = sm + SM_BUF + t * TS;

    int e = blockIdx.x * 256 + t;
    if (e >= n_edges) return;

    int r = edges[e];
    int c = edges[n_edges + e];

    float d0 = coord[3*r+0] - coord[3*c+0];
    float d1 = coord[3*r+1] - coord[3*c+1];
    float d2 = coord[3*r+2] - coord[3*c+2];
    float radial = d0*d0 + d1*d1 + d2*d2;

    const float4* pr = (const float4*)(g_preR + (size_t)r * 128);
    const float4* pc = (const float4*)(g_preC + (size_t)c * 128);

    // ---- attention gate: stream over PA halves ----
    float s_att = sm[SM_MISC + 448];
#pragma unroll 4
    for (int j = 0; j < 16; j++) {
        float4 a4 = __ldg(&pr[16 + j]);
        float4 b4 = __ldg(&pc[16 + j]);
        s_att += tshrink(a4.x + b4.x + ab1s[4*j+0]) * aW2s[4*j+0];
        s_att += tshrink(a4.y + b4.y + ab1s[4*j+1]) * aW2s[4*j+1];
        s_att += tshrink(a4.z + b4.z + ab1s[4*j+2]) * aW2s[4*j+2];
        s_att += tshrink(a4.w + b4.w + ab1s[4*j+3]) * aW2s[4*j+3];
    }
    float gate = sigmoidf_fast(s_att);

    // ---- hidden: stage tanhshrink(u) for edge-MLP L2 ----
#pragma unroll 4
    for (int j = 0; j < 16; j++) {
        float4 a4 = __ldg(&pr[j]);
        float4 b4 = __ldg(&pc[j]);
        my[4*j+0] = tshrink(a4.x + b4.x + radial * w128s[4*j+0] + eb1s[4*j+0]);
        my[4*j+1] = tshrink(a4.y + b4.y + radial * w128s[4*j+1] + eb1s[4*j+1]);
        my[4*j+2] = tshrink(a4.z + b4.z + radial * w128s[4*j+2] + eb1s[4*j+2]);
        my[4*j+3] = tshrink(a4.w + b4.w + radial * w128s[4*j+3] + eb1s[4*j+3]);
    }

    // ---- edge MLP layer 2 (GEMV, shared weights) ----
    float acc[64];
#pragma unroll
    for (int j = 0; j < 64; j++) acc[j] = eb2s[j];
#pragma unroll 2
    for (int k = 0; k < 64; k++) fma_one_sh(my[k], sm + SM_W2 + k * 64, acc);

    // ---- gate + scatter edge_feat, restage ----
    float* aggRow = g_agg + (size_t)r * 64;
#pragma unroll
    for (int j = 0; j < 16; j++) {
        float f0 = tshrink(acc[4*j+0]) * gate;
        float f1 = tshrink(acc[4*j+1]) * gate;
        float f2 = tshrink(acc[4*j+2]) * gate;
        float f3 = tshrink(acc[4*j+3]) * gate;
        my[4*j+0] = f0; my[4*j+1] = f1; my[4*j+2] = f2; my[4*j+3] = f3;
        asm volatile("red.global.add.v4.f32 [%0], {%1,%2,%3,%4};"
                     :: "l"(aggRow + 4*j), "f"(f0), "f"(f1), "f"(f2), "f"(f3)
                     : "memory");
    }

    // ---- coord MLP layer 1 (GEMV, shared weights) ----
#pragma unroll
    for (int j = 0; j < 64; j++) acc[j] = cb1s[j];
#pragma unroll 2
    for (int k = 0; k < 64; k++) fma_one_sh(my[k], sm + SM_C1 + k * 64, acc);

    // ---- coord scalar + scatter ----
    float sc = sm[SM_MISC + 449];
#pragma unroll
    for (int k = 0; k < 64; k++) sc += tshrink(acc[k]) * cW2s[k];

    atomicAdd(&coord_out[3*r+0], d0 * sc);
    atomicAdd(&coord_out[3*r+1], d1 * sc);
    atomicAdd(&coord_out[3*r+2], d2 * sc);
}

// ---------------------------------------------------------------------------
// Node kernel: out = nodes + tanhshrink([nodes|agg] @ nW1 + nb1) @ nW2 + nb2
// nW1 staged in shared (32 KB); nW2 via __ldg (keeps 2 blocks/SM).
// ---------------------------------------------------------------------------
__global__ __launch_bounds__(256) void node_kernel(
    const float* __restrict__ nodes,
    const float* __restrict__ nW1, const float* __restrict__ nb1,
    const float* __restrict__ nW2, const float* __restrict__ nb2,
    float* __restrict__ out, int n) {
    extern __shared__ float sm[];
    float* sW1 = sm;            // 128x64 = 8192 floats
    float* stage = sm + 8192;   // 256*TS

    int t = threadIdx.x;
    for (int i = t; i < 8192; i += 256) sW1[i] = nW1[i];
    __syncthreads();

    float* my = stage + t * TS;
    int i = blockIdx.x * 256 + t;
    if (i >= n) return;

    float acc[64];
    init_from_bias(nb1, acc);
    const float4* nod4 = (const float4*)nodes;
    const float4* agg4 = (const float4*)g_agg;
    size_t base = (size_t)i * 16;

    // stage nodes row, GEMV half 1
#pragma unroll
    for (int j = 0; j < 16; j++) {
        float4 v = __ldg(&nod4[base + j]);
        my[4*j+0] = v.x; my[4*j+1] = v.y; my[4*j+2] = v.z; my[4*j+3] = v.w;
    }
#pragma unroll 2
    for (int k = 0; k < 64; k++) fma_one_sh(my[k], sW1 + k * 64, acc);

    // stage agg row, GEMV half 2
#pragma unroll
    for (int j = 0; j < 16; j++) {
        float4 v = agg4[base + j];
        my[4*j+0] = v.x; my[4*j+1] = v.y; my[4*j+2] = v.z; my[4*j+3] = v.w;
    }
#pragma unroll 2
    for (int k = 0; k < 64; k++) fma_one_sh(my[k], sW1 + (64 + k) * 64, acc);

    // activation into staging, second GEMV (weights via __ldg)
#pragma unroll
    for (int k = 0; k < 64; k++) my[k] = tshrink(acc[k]);
    init_from_bias(nb2, acc);
#pragma unroll 2
    for (int k = 0; k < 64; k++) fma_one_g(my[k], nW2 + k * 64, acc);

    // residual + write
    float4* o4 = (float4*)out;
#pragma unroll
    for (int j = 0; j < 16; j++) {
        float4 nv = __ldg(&nod4[base + j]);
        float4 w = make_float4(nv.x + acc[4*j+0], nv.y + acc[4*j+1],
                               nv.z + acc[4*j+2], nv.w + acc[4*j+3]);
        o4[base + j] = w;
    }
}

// ---------------------------------------------------------------------------
extern "C" void kernel_launch(void* const* d_in, const int* in_sizes, int n_in,
                              void* d_out, int out_size) {
    const float* nodes = (const float*)d_in[0];
    const float* coord = (const float*)d_in[1];
    const int*   edges = (const int*)d_in[2];
    const float* eW1 = (const float*)d_in[3];
    const float* eb1 = (const float*)d_in[4];
    const float* eW2 = (const float*)d_in[5];
    const float* eb2 = (const float*)d_in[6];
    const float* aW1 = (const float*)d_in[7];
    const float* ab1 = (const float*)d_in[8];
    const float* aW2 = (const float*)d_in[9];
    const float* ab2 = (const float*)d_in[10];
    const float* nW1 = (const float*)d_in[11];
    const float* nb1 = (const float*)d_in[12];
    const float* nW2 = (const float*)d_in[13];
    const float* nb2 = (const float*)d_in[14];
    const float* cW1 = (const float*)d_in[15];
    const float* cb1 = (const float*)d_in[16];
    const float* cW2 = (const float*)d_in[17];
    const float* cb2 = (const float*)d_in[18];

    int n = in_sizes[0] / NFEAT;            // 50000
    int n_edges = in_sizes[2] / 2;          // 800000

    float* out = (float*)d_out;
    float* nodes_out = out;
    float* coord_out = out + (size_t)n * NFEAT;

    const size_t smem_pre  = (size_t)(8192 + 256 * TS) * sizeof(float);   // 98.5 KB
    const size_t smem_edge = (size_t)(8704 + 256 * TS) * sizeof(float);   // ~101 KB
    const size_t smem_node = (size_t)(8192 + 256 * TS) * sizeof(float);   // 98.5 KB
    cudaFuncSetAttribute(pre_kernel,  cudaFuncAttributeMaxDynamicSharedMemorySize, (int)smem_pre);
    cudaFuncSetAttribute(edge_kernel, cudaFuncAttributeMaxDynamicSharedMemorySize, (int)smem_edge);
    cudaFuncSetAttribute(node_kernel, cudaFuncAttributeMaxDynamicSharedMemorySize, (int)smem_node);

    int init_blocks = (n * NFEAT + 255) / 256;
    init_kernel<<<init_blocks, 256>>>(coord, coord_out, n);

    int nblocks = (n + 255) / 256;
    dim3 pre_grid(nblocks, 2);
    pre_kernel<<<pre_grid, 256, smem_pre>>>(nodes, eW1, aW1, n);

    int edge_blocks = (n_edges + 255) / 256;
    edge_kernel<<<edge_blocks, 256, smem_edge>>>(
        coord, edges,
        eW1, eb1, eW2, eb2,
        ab1, aW2, ab2,
        cW1, cb1, cW2, cb2,
        coord_out, n_edges);

    node_kernel<<<nblocks, 256, smem_node>>>(
        nodes, nW1, nb1, nW2, nb2, nodes_out, n);
}